// round 3
// baseline (speedup 1.0000x reference)
#include <cuda_runtime.h>

// Problem constants
static constexpr int N_MC = 32;
static constexpr int M    = 8192;
static constexpr int D    = 16;

#define TWOPI_F   6.2831853071795864769f   // rounds to float32(2*pi)
#define INV2PI_F  0.15915494309189535f
#define NEG_HALF_LOG_2PI -0.9189385332046727f
#define C_EX2     (-0.72134752044448170368f)  // -0.5 * log2(e)
#define LN2_F     0.69314718055994530942f
#define K2PILOG2E 9.0647202836543873894f      // 2*pi * log2(e)

// Scratch: per-(m,d) (scale, 1/scale), wrap weight w = exp(-a^2/2) with a = 2pi/s,
// and per-m constant C_m = sum_d log_norm.
__device__ float2 g_sinv[M * D];
__device__ float  g_w[M * D];
__device__ float  g_C[M];

__device__ __forceinline__ float ex2f(float x) {
    float y; asm("ex2.approx.f32 %0, %1;" : "=f"(y) : "f"(x)); return y;
}
__device__ __forceinline__ float lg2f(float x) {
    float y; asm("lg2.approx.f32 %0, %1;" : "=f"(y) : "f"(x)); return y;
}

// Pass 1: 131072 threads. scale = softplus(raw) computed EXACTLY as
// jax.nn.softplus = max(x,0) + log1p(exp(-|x|)) with precise libdevice
// expf/log1pf so x = eps*scale (and the mod boundary) bit-matches XLA.
// Everything else here only feeds lq (loose tolerance) -> fast paths OK.
__global__ void relie_prep(const float* __restrict__ gamma_raw) {
    int tid = blockIdx.x * blockDim.x + threadIdx.x;   // 0 .. M*D-1
    float raw = gamma_raw[tid];
    float s   = fmaxf(raw, 0.0f) + log1pf(expf(-fabsf(raw)));
    float inv = 1.0f / s;
    float a   = TWOPI_F * inv;
    float w   = ex2f(a * a * C_EX2);                   // exp(-a^2/2)
    float ln  = NEG_HALF_LOG_2PI - LN2_F * lg2f(s);
    g_sinv[tid] = make_float2(s, inv);
    g_w[tid]    = w;
    ln += __shfl_xor_sync(0xffffffffu, ln, 1);
    ln += __shfl_xor_sync(0xffffffffu, ln, 2);
    ln += __shfl_xor_sync(0xffffffffu, ln, 4);
    ln += __shfl_xor_sync(0xffffffffu, ln, 8);
    if ((tid & 15) == 0) g_C[tid >> 4] = ln;
}

// Pass 2: N*M*4 threads; each thread owns 4 consecutive dims of one (n,m).
//
// Lattice-sum refactor:  sum_{k=-1,0,1} e^{-(u+ka)^2/2}
//   = e^{-u^2/2} * (1 + w*(e^{au} + e^{-au})),  w = e^{-a^2/2}.
// The leading Gaussian needs NO exp (contributes -0.5*sum u^2 via FMA), and
// the residual factors p_j in (1, 2.01] multiply across the 4 dims -> ONE
// lg2 per thread.  Corner bound: w*e^{a|u|} <= e^{-a^2/2 + a*pi/s} = 1, so
// no overflow and the product stays in (1,16].
__global__ void __launch_bounds__(256) relie_main(
    const float4* __restrict__ eps4,   // N*M*4 float4
    const float4* __restrict__ mu4,    // M*4 float4
    float4*       __restrict__ g4,     // N*M*4 float4
    float*        __restrict__ lq)     // N*M floats
{
    int gid = blockIdx.x * blockDim.x + threadIdx.x;   // 0 .. N*M*4-1
    int nm  = gid >> 2;
    int dq  = gid & 3;
    int m   = nm & (M - 1);

    float4 e  = eps4[gid];
    float4 mu = mu4[(m << 2) + dq];
    const float4* sv = reinterpret_cast<const float4*>(g_sinv);
    float4 s01 = sv[(m << 3) + (dq << 1)];       // (s0,i0,s1,i1)
    float4 s23 = sv[(m << 3) + (dq << 1) + 1];   // (s2,i2,s3,i3)
    float4 w4  = reinterpret_cast<const float4*>(g_w)[(m << 2) + dq];

    float ev[4] = { e.x, e.y, e.z, e.w };
    float mv[4] = { mu.x, mu.y, mu.z, mu.w };
    float ss[4] = { s01.x, s01.z, s23.x, s23.z };
    float iv[4] = { s01.y, s01.w, s23.y, s23.w };
    float wv[4] = { w4.x, w4.y, w4.z, w4.w };
    float gv[4];

    float P    = 1.0f;   // product of residual factors
    float uacc = 0.0f;   // sum of u^2
    #pragma unroll
    for (int j = 0; j < 4; j++) {
        float x = ev[j] * ss[j];

        // ---- g = mod(x + mu, 2pi), bit-identical to exact fmodf + fixup ----
        // (validated in R1/R2: rel_err floor 5e-8, zero 2pi flips)
        float v = x + mv[j];
        float q = rintf(v * INV2PI_F);
        float t = fmaf(q, -TWOPI_F, v);
        if (t < 0.0f) t += TWOPI_F;
        gv[j] = t;

        // ---- lq: center x into [-pi,pi], residual-factor form ----
        float qr = rintf(x * INV2PI_F);
        float r  = fmaf(qr, -TWOPI_F, x);
        float u  = r * iv[j];
        uacc = fmaf(u, u, uacc);
        float c  = (iv[j] * K2PILOG2E) * u;          // a*u*log2(e)
        float t1 = ex2f(c);
        float t2 = ex2f(-c);
        P *= fmaf(wv[j], t1 + t2, 1.0f);
    }

    g4[gid] = make_float4(gv[0], gv[1], gv[2], gv[3]);

    // lq contribution of this thread's 4 dims:
    float val = fmaf(uacc, -0.5f, LN2_F * lg2f(P));

    // Reduce across the 4 lanes owning this (n,m)
    val += __shfl_xor_sync(0xffffffffu, val, 1);
    val += __shfl_xor_sync(0xffffffffu, val, 2);
    if (dq == 0) lq[nm] = val + g_C[m];
}

extern "C" void kernel_launch(void* const* d_in, const int* in_sizes, int n_in,
                              void* d_out, int out_size) {
    const float* eps       = (const float*)d_in[0];  // (32, 8192, 16)
    const float* gamma_raw = (const float*)d_in[1];  // (8192, 16)
    const float* mu        = (const float*)d_in[2];  // (8192, 16)

    float* g_out  = (float*)d_out;                          // N*M*D floats
    float* lq_out = (float*)d_out + (size_t)N_MC * M * D;   // N*M floats

    relie_prep<<<(M * D) / 256, 256>>>(gamma_raw);
    relie_main<<<(N_MC * M * 4) / 256, 256>>>(
        (const float4*)eps, (const float4*)mu, (float4*)g_out, lq_out);
}

// round 4
// speedup vs baseline: 1.0270x; 1.0270x over previous
#include <cuda_runtime.h>

// Problem constants
static constexpr int N_MC = 32;
static constexpr int M    = 8192;
static constexpr int D    = 16;

#define TWOPI_F   6.2831853071795864769f   // rounds to float32(2*pi)
#define INV2PI_F  0.15915494309189535f
#define NEG_HALF_LOG_2PI -0.9189385332046727f
#define C_EX2     (-0.72134752044448170368f)  // -0.5 * log2(e)
#define LN2_F     0.69314718055994530942f
#define LOG2E_F   1.4426950408889634074f
#define MAGIC_F   12582912.0f                 // 1.5 * 2^23

// Per-(m,d) constants, SoA so main-kernel loads are dense float4:
//   S = scale, I2 = 1/scale^2, W = exp(-a^2/2), B = a*log2(e)/scale,  a = 2pi/scale
__device__ float g_S [M * D];
__device__ float g_I2[M * D];
__device__ float g_W [M * D];
__device__ float g_B [M * D];
__device__ float g_C [M];          // per-m sum of log-normalizers

__device__ __forceinline__ float ex2f(float x) {
    float y; asm("ex2.approx.f32 %0, %1;" : "=f"(y) : "f"(x)); return y;
}
__device__ __forceinline__ float lg2f(float x) {
    float y; asm("lg2.approx.f32 %0, %1;" : "=f"(y) : "f"(x)); return y;
}

// Pass 1: 131072 threads. scale = softplus(raw) computed EXACTLY as
// jax.nn.softplus = max(x,0) + log1p(exp(-|x|)) with precise libdevice
// expf/log1pf so x = eps*scale (and the mod boundary) bit-matches XLA.
__global__ void relie_prep(const float* __restrict__ gamma_raw) {
    int tid = blockIdx.x * blockDim.x + threadIdx.x;   // 0 .. M*D-1
    float raw = gamma_raw[tid];
    float s   = fmaxf(raw, 0.0f) + log1pf(expf(-fabsf(raw)));
    float inv = 1.0f / s;
    float a   = TWOPI_F * inv;
    g_S [tid] = s;
    g_I2[tid] = inv * inv;
    g_W [tid] = ex2f(a * a * C_EX2);      // exp(-a^2/2)
    g_B [tid] = a * inv * LOG2E_F;        // so c = r*B = (a*u)*log2(e)
    float ln  = NEG_HALF_LOG_2PI - LN2_F * lg2f(s);
    ln += __shfl_xor_sync(0xffffffffu, ln, 1);
    ln += __shfl_xor_sync(0xffffffffu, ln, 2);
    ln += __shfl_xor_sync(0xffffffffu, ln, 4);
    ln += __shfl_xor_sync(0xffffffffu, ln, 8);
    if ((tid & 15) == 0) g_C[tid >> 4] = ln;
}

// Pass 2: 524288 threads.  Thread t owns dims [4*dq, 4*dq+4) of TWO (n,m)
// pairs sharing the same m:  element A = t, element B = t + 2^19 (n vs n+16).
// Constants and mu are loaded once and used twice; the A/B chains are fully
// independent -> 2x ILP; every load/store is dense float4-coalesced.
__global__ void __launch_bounds__(256, 5) relie_main(
    const float4* __restrict__ eps4,   // 2^20 float4
    const float4* __restrict__ mu4,    // M*4 float4
    float4*       __restrict__ g4,     // 2^20 float4
    float*        __restrict__ lq)     // N*M floats
{
    int t    = blockIdx.x * blockDim.x + threadIdx.x;  // 0 .. 2^19-1
    int nmA  = t >> 2;
    int dq   = t & 3;
    int m    = nmA & (M - 1);
    int gidB = t + (1 << 19);
    int nmB  = nmA + (1 << 17);
    int ci   = (m << 2) + dq;

    float4 eA = eps4[t];
    float4 eB = eps4[gidB];
    float4 mu = mu4[ci];
    float4 S  = reinterpret_cast<const float4*>(g_S )[ci];
    float4 I2 = reinterpret_cast<const float4*>(g_I2)[ci];
    float4 W  = reinterpret_cast<const float4*>(g_W )[ci];
    float4 B  = reinterpret_cast<const float4*>(g_B )[ci];

    float evA[4] = { eA.x, eA.y, eA.z, eA.w };
    float evB[4] = { eB.x, eB.y, eB.z, eB.w };
    float mv[4]  = { mu.x, mu.y, mu.z, mu.w };
    float sv[4]  = { S.x,  S.y,  S.z,  S.w  };
    float iv[4]  = { I2.x, I2.y, I2.z, I2.w };
    float wv[4]  = { W.x,  W.y,  W.z,  W.w  };
    float bv[4]  = { B.x,  B.y,  B.z,  B.w  };
    float gA[4], gB[4];

    float PA = 1.0f, PB = 1.0f;    // residual-factor products
    float uA = 0.0f, uB = 0.0f;    // sum of (r/s)^2
    #pragma unroll
    for (int j = 0; j < 4; j++) {
        float xA = evA[j] * sv[j];
        float xB = evB[j] * sv[j];

        // ---- g = mod(x+mu, 2pi): magic-number nearest-int + exact fma ----
        // (same exactness argument validated in R1-R3; zero 2pi-flip risk)
        float vA = xA + mv[j];
        float qA = __fadd_rn(__fmaf_rn(vA, INV2PI_F, MAGIC_F), -MAGIC_F);
        float tA = __fmaf_rn(qA, -TWOPI_F, vA);
        if (tA < 0.0f) tA += TWOPI_F;
        gA[j] = tA;
        float vB = xB + mv[j];
        float qB = __fadd_rn(__fmaf_rn(vB, INV2PI_F, MAGIC_F), -MAGIC_F);
        float tB = __fmaf_rn(qB, -TWOPI_F, vB);
        if (tB < 0.0f) tB += TWOPI_F;
        gB[j] = tB;

        // ---- lq: center x, residual-factor 3-term lattice sum ----
        // sum_{k=-1,0,1} e^{-(u+ka)^2/2} = e^{-u^2/2} (1 + w(e^{au}+e^{-au}))
        float kA = __fadd_rn(__fmaf_rn(xA, INV2PI_F, MAGIC_F), -MAGIC_F);
        float rA = __fmaf_rn(kA, -TWOPI_F, xA);
        uA = fmaf(rA * rA, iv[j], uA);
        float cA = rA * bv[j];
        PA *= fmaf(wv[j], ex2f(cA) + ex2f(-cA), 1.0f);

        float kB = __fadd_rn(__fmaf_rn(xB, INV2PI_F, MAGIC_F), -MAGIC_F);
        float rB = __fmaf_rn(kB, -TWOPI_F, xB);
        uB = fmaf(rB * rB, iv[j], uB);
        float cB = rB * bv[j];
        PB *= fmaf(wv[j], ex2f(cB) + ex2f(-cB), 1.0f);
    }

    g4[t]    = make_float4(gA[0], gA[1], gA[2], gA[3]);
    g4[gidB] = make_float4(gB[0], gB[1], gB[2], gB[3]);

    float valA = fmaf(uA, -0.5f, LN2_F * lg2f(PA));
    float valB = fmaf(uB, -0.5f, LN2_F * lg2f(PB));
    valA += __shfl_xor_sync(0xffffffffu, valA, 1);
    valA += __shfl_xor_sync(0xffffffffu, valA, 2);
    valB += __shfl_xor_sync(0xffffffffu, valB, 1);
    valB += __shfl_xor_sync(0xffffffffu, valB, 2);
    if (dq == 0) {
        float C = g_C[m];
        lq[nmA] = valA + C;
        lq[nmB] = valB + C;
    }
}

extern "C" void kernel_launch(void* const* d_in, const int* in_sizes, int n_in,
                              void* d_out, int out_size) {
    const float* eps       = (const float*)d_in[0];  // (32, 8192, 16)
    const float* gamma_raw = (const float*)d_in[1];  // (8192, 16)
    const float* mu        = (const float*)d_in[2];  // (8192, 16)

    float* g_out  = (float*)d_out;                          // N*M*D floats
    float* lq_out = (float*)d_out + (size_t)N_MC * M * D;   // N*M floats

    relie_prep<<<(M * D) / 256, 256>>>(gamma_raw);
    relie_main<<<(1 << 19) / 256, 256>>>(
        (const float4*)eps, (const float4*)mu, (float4*)g_out, lq_out);
}

// round 5
// speedup vs baseline: 1.0450x; 1.0175x over previous
#include <cuda_runtime.h>

// Problem constants
static constexpr int N_MC = 32;
static constexpr int M    = 8192;
static constexpr int D    = 16;

#define TWOPI_F   6.2831853071795864769f   // rounds to float32(2*pi)
#define INV2PI_F  0.15915494309189535f
#define NEG_HALF_LOG_2PI -0.9189385332046727f
#define C_EX2     (-0.72134752044448170368f)  // -0.5 * log2(e)
#define LN2_F     0.69314718055994530942f
#define LOG2E_F   1.4426950408889634074f
#define MAGIC_F   12582912.0f                 // 1.5 * 2^23

typedef unsigned long long u64;

// Packed f32x2 broadcast constants (same f32 bits in both lanes)
#define MG2     0x4B4000004B400000ull   // ( MAGIC,  MAGIC)
#define NMG2    0xCB400000CB400000ull   // (-MAGIC, -MAGIC)
#define INV2PI2 0x3E22F9833E22F983ull   // (1/2pi, 1/2pi)
#define NTWOPI2 0xC0C90FDBC0C90FDBull   // (-2pi, -2pi)
#define ONE2    0x3F8000003F800000ull   // (1, 1)

// Per-(m,d) constants, SoA so main-kernel loads are dense float4:
//   S = scale, I2 = 1/scale^2, W = exp(-a^2/2), B = a*log2(e)/scale, a = 2pi/scale
__device__ float g_S [M * D];
__device__ float g_I2[M * D];
__device__ float g_W [M * D];
__device__ float g_B [M * D];
__device__ float g_C [M];          // per-m sum of log-normalizers

__device__ __forceinline__ float ex2f(float x) {
    float y; asm("ex2.approx.f32 %0, %1;" : "=f"(y) : "f"(x)); return y;
}
__device__ __forceinline__ float lg2f(float x) {
    float y; asm("lg2.approx.f32 %0, %1;" : "=f"(y) : "f"(x)); return y;
}
__device__ __forceinline__ u64 pk(float lo, float hi) {
    u64 r; asm("mov.b64 %0, {%1, %2};" : "=l"(r) : "f"(lo), "f"(hi)); return r;
}
__device__ __forceinline__ void upk(float& lo, float& hi, u64 v) {
    asm("mov.b64 {%0, %1}, %2;" : "=f"(lo), "=f"(hi) : "l"(v));
}
__device__ __forceinline__ u64 fma2(u64 a, u64 b, u64 c) {
    u64 d; asm("fma.rn.f32x2 %0, %1, %2, %3;" : "=l"(d) : "l"(a), "l"(b), "l"(c)); return d;
}
__device__ __forceinline__ u64 add2(u64 a, u64 b) {
    u64 d; asm("add.rn.f32x2 %0, %1, %2;" : "=l"(d) : "l"(a), "l"(b)); return d;
}
__device__ __forceinline__ u64 mul2(u64 a, u64 b) {
    u64 d; asm("mul.rn.f32x2 %0, %1, %2;" : "=l"(d) : "l"(a), "l"(b)); return d;
}

// Pass 1: 131072 threads. scale = softplus(raw) computed EXACTLY as
// jax.nn.softplus = max(x,0) + log1p(exp(-|x|)) with precise libdevice
// expf/log1pf so x = eps*scale (and the mod boundary) bit-matches XLA.
__global__ void relie_prep(const float* __restrict__ gamma_raw) {
    int tid = blockIdx.x * blockDim.x + threadIdx.x;   // 0 .. M*D-1
    float raw = gamma_raw[tid];
    float s   = fmaxf(raw, 0.0f) + log1pf(expf(-fabsf(raw)));
    float inv = 1.0f / s;
    float a   = TWOPI_F * inv;
    g_S [tid] = s;
    g_I2[tid] = inv * inv;
    g_W [tid] = ex2f(a * a * C_EX2);      // exp(-a^2/2)
    g_B [tid] = a * inv * LOG2E_F;        // c = r*B = (a*u)*log2(e)
    float ln  = NEG_HALF_LOG_2PI - LN2_F * lg2f(s);
    ln += __shfl_xor_sync(0xffffffffu, ln, 1);
    ln += __shfl_xor_sync(0xffffffffu, ln, 2);
    ln += __shfl_xor_sync(0xffffffffu, ln, 4);
    ln += __shfl_xor_sync(0xffffffffu, ln, 8);
    if ((tid & 15) == 0) g_C[tid >> 4] = ln;
}

// One dim-PAIR (two adjacent dims of one element), fully packed f32x2.
//   g: magic-rint + fma remainder (per-lane IEEE rn == scalar path; the
//      scalar fixup happens after the unpack the float4 store needs anyway)
//   lq: 2-term lattice sum  p = 1 + w*exp(a|u|)   (dropped term <= w <= 1.6e-4)
__device__ __forceinline__ void dimpair(
    u64 e2, u64 s2, u64 mu2, u64 i2, u64 b2, u64 w2,
    float& g_lo, float& g_hi, u64& uacc2, u64& P2)
{
    u64 x2 = mul2(e2, s2);
    // ---- g path ----
    u64 v2 = add2(x2, mu2);
    u64 q2 = add2(fma2(v2, INV2PI2, MG2), NMG2);
    u64 t2 = fma2(q2, NTWOPI2, v2);
    float tl, th; upk(tl, th, t2);
    if (tl < 0.0f) tl += TWOPI_F;
    if (th < 0.0f) th += TWOPI_F;
    g_lo = tl; g_hi = th;
    // ---- lq path ----
    u64 k2  = add2(fma2(x2, INV2PI2, MG2), NMG2);
    u64 r2  = fma2(k2, NTWOPI2, x2);
    u64 rr2 = mul2(r2, r2);
    uacc2 = fma2(rr2, i2, uacc2);
    u64 c2 = mul2(r2, b2);
    float cl, ch; upk(cl, ch, c2);
    float el = ex2f(fabsf(cl));          // |.| folds into MUFU operand
    float eh = ex2f(fabsf(ch));
    P2 = mul2(P2, fma2(w2, pk(el, eh), ONE2));
}

// Pass 2: 524288 threads.  Thread t owns dims [4*dq,4*dq+4) of TWO (n,m)
// pairs sharing the same m: A = t, B = t + 2^19 (n vs n+16).  All loads and
// stores dense float4; all per-dim math packed f32x2.
__global__ void __launch_bounds__(256) relie_main(
    const float4* __restrict__ eps4,   // 2^20 float4
    const float4* __restrict__ mu4,    // M*4 float4
    float4*       __restrict__ g4,     // 2^20 float4
    float*        __restrict__ lq)     // N*M floats
{
    int t    = blockIdx.x * blockDim.x + threadIdx.x;  // 0 .. 2^19-1
    int nmA  = t >> 2;
    int dq   = t & 3;
    int m    = nmA & (M - 1);
    int gidB = t + (1 << 19);
    int nmB  = nmA + (1 << 17);
    int ci   = (m << 2) + dq;

    float4 eA = eps4[t];
    float4 eB = eps4[gidB];
    float4 mu = mu4[ci];
    float4 S  = reinterpret_cast<const float4*>(g_S )[ci];
    float4 I2 = reinterpret_cast<const float4*>(g_I2)[ci];
    float4 W  = reinterpret_cast<const float4*>(g_W )[ci];
    float4 B  = reinterpret_cast<const float4*>(g_B )[ci];

    // Pack per-dim constant pairs once; shared by elements A and B.
    u64 s01 = pk(S.x,  S.y),  s23 = pk(S.z,  S.w);
    u64 m01 = pk(mu.x, mu.y), m23 = pk(mu.z, mu.w);
    u64 i01 = pk(I2.x, I2.y), i23 = pk(I2.z, I2.w);
    u64 b01 = pk(B.x,  B.y),  b23 = pk(B.z,  B.w);
    u64 w01 = pk(W.x,  W.y),  w23 = pk(W.z,  W.w);

    float4 gA, gB;
    u64 uA2 = 0, uB2 = 0;            // (+0,+0) packed
    u64 PA2 = ONE2, PB2 = ONE2;

    dimpair(pk(eA.x, eA.y), s01, m01, i01, b01, w01, gA.x, gA.y, uA2, PA2);
    dimpair(pk(eA.z, eA.w), s23, m23, i23, b23, w23, gA.z, gA.w, uA2, PA2);
    dimpair(pk(eB.x, eB.y), s01, m01, i01, b01, w01, gB.x, gB.y, uB2, PB2);
    dimpair(pk(eB.z, eB.w), s23, m23, i23, b23, w23, gB.z, gB.w, uB2, PB2);

    g4[t]    = gA;
    g4[gidB] = gB;

    float u0, u1, p0, p1;
    upk(u0, u1, uA2); upk(p0, p1, PA2);
    float valA = fmaf(u0 + u1, -0.5f, LN2_F * lg2f(p0 * p1));
    upk(u0, u1, uB2); upk(p0, p1, PB2);
    float valB = fmaf(u0 + u1, -0.5f, LN2_F * lg2f(p0 * p1));

    valA += __shfl_xor_sync(0xffffffffu, valA, 1);
    valA += __shfl_xor_sync(0xffffffffu, valA, 2);
    valB += __shfl_xor_sync(0xffffffffu, valB, 1);
    valB += __shfl_xor_sync(0xffffffffu, valB, 2);
    if (dq == 0) {
        float C = g_C[m];
        lq[nmA] = valA + C;
        lq[nmB] = valB + C;
    }
}

extern "C" void kernel_launch(void* const* d_in, const int* in_sizes, int n_in,
                              void* d_out, int out_size) {
    const float* eps       = (const float*)d_in[0];  // (32, 8192, 16)
    const float* gamma_raw = (const float*)d_in[1];  // (8192, 16)
    const float* mu        = (const float*)d_in[2];  // (8192, 16)

    float* g_out  = (float*)d_out;                          // N*M*D floats
    float* lq_out = (float*)d_out + (size_t)N_MC * M * D;   // N*M floats

    relie_prep<<<(M * D) / 256, 256>>>(gamma_raw);
    relie_main<<<(1 << 19) / 256, 256>>>(
        (const float4*)eps, (const float4*)mu, (float4*)g_out, lq_out);
}

// round 6
// speedup vs baseline: 1.2222x; 1.1696x over previous
#include <cuda_runtime.h>

// Problem constants
static constexpr int N_MC = 32;
static constexpr int M    = 8192;
static constexpr int D    = 16;

#define TWOPI_F   6.2831853071795864769f   // rounds to float32(2*pi)
#define NEG_HALF_LOG_2PI -0.9189385332046727f
#define C_EX2     (-0.72134752044448170368f)  // -0.5 * log2(e)
#define LN2_F     0.69314718055994530942f
#define LOG2E_F   1.4426950408889634074f

typedef unsigned long long u64;

// Packed f32x2 broadcast constants (same f32 bits in both lanes)
#define MG2     0x4B4000004B400000ull   // ( 1.5*2^23,  1.5*2^23)
#define NMG2    0xCB400000CB400000ull   // (-1.5*2^23, -1.5*2^23)
#define INV2PI2 0x3E22F9833E22F983ull   // (1/2pi, 1/2pi)
#define NTWOPI2 0xC0C90FDBC0C90FDBull   // (-2pi, -2pi)
#define ONE2    0x3F8000003F800000ull   // (1, 1)

// Per-(m,d) constants, SoA so main-kernel loads are dense float4:
//   S = scale, I2 = 1/scale^2, W = exp(-a^2/2), B = a*log2(e)/scale, a = 2pi/scale
__device__ float g_S [M * D];
__device__ float g_I2[M * D];
__device__ float g_W [M * D];
__device__ float g_B [M * D];
__device__ float g_C [M];          // per-m sum of log-normalizers

__device__ __forceinline__ float ex2f(float x) {
    float y; asm("ex2.approx.f32 %0, %1;" : "=f"(y) : "f"(x)); return y;
}
__device__ __forceinline__ float lg2f(float x) {
    float y; asm("lg2.approx.f32 %0, %1;" : "=f"(y) : "f"(x)); return y;
}
__device__ __forceinline__ u64 pk(float lo, float hi) {
    u64 r; asm("mov.b64 %0, {%1, %2};" : "=l"(r) : "f"(lo), "f"(hi)); return r;
}
__device__ __forceinline__ void upk(float& lo, float& hi, u64 v) {
    asm("mov.b64 {%0, %1}, %2;" : "=f"(lo), "=f"(hi) : "l"(v));
}
__device__ __forceinline__ u64 fma2(u64 a, u64 b, u64 c) {
    u64 d; asm("fma.rn.f32x2 %0, %1, %2, %3;" : "=l"(d) : "l"(a), "l"(b), "l"(c)); return d;
}
__device__ __forceinline__ u64 add2(u64 a, u64 b) {
    u64 d; asm("add.rn.f32x2 %0, %1, %2;" : "=l"(d) : "l"(a), "l"(b)); return d;
}
__device__ __forceinline__ u64 mul2(u64 a, u64 b) {
    u64 d; asm("mul.rn.f32x2 %0, %1, %2;" : "=l"(d) : "l"(a), "l"(b)); return d;
}

// Pass 1: 131072 threads. scale = softplus(raw) computed EXACTLY as
// jax.nn.softplus = max(x,0) + log1p(exp(-|x|)) with precise libdevice
// expf/log1pf so x = eps*scale (and the mod boundary) bit-matches XLA.
__global__ void relie_prep(const float* __restrict__ gamma_raw) {
    int tid = blockIdx.x * blockDim.x + threadIdx.x;   // 0 .. M*D-1
    float raw = gamma_raw[tid];
    float s   = fmaxf(raw, 0.0f) + log1pf(expf(-fabsf(raw)));
    float inv = 1.0f / s;
    float a   = TWOPI_F * inv;
    g_S [tid] = s;
    g_I2[tid] = inv * inv;
    g_W [tid] = ex2f(a * a * C_EX2);      // exp(-a^2/2)
    g_B [tid] = a * inv * LOG2E_F;        // c = r*B = (a*u)*log2(e)
    float ln  = NEG_HALF_LOG_2PI - LN2_F * lg2f(s);
    ln += __shfl_xor_sync(0xffffffffu, ln, 1);
    ln += __shfl_xor_sync(0xffffffffu, ln, 2);
    ln += __shfl_xor_sync(0xffffffffu, ln, 4);
    ln += __shfl_xor_sync(0xffffffffu, ln, 8);
    if ((tid & 15) == 0) g_C[tid >> 4] = ln;
}

// One dim-PAIR, fully packed f32x2 (validated R5: g bit-safe, lq 2-term).
__device__ __forceinline__ void dimpair(
    u64 e2, u64 s2, u64 mu2, u64 i2, u64 b2, u64 w2,
    float& g_lo, float& g_hi, u64& uacc2, u64& P2)
{
    u64 x2 = mul2(e2, s2);
    // ---- g = mod(x+mu, 2pi): magic-rint + exact fma remainder ----
    u64 v2 = add2(x2, mu2);
    u64 q2 = add2(fma2(v2, INV2PI2, MG2), NMG2);
    u64 t2 = fma2(q2, NTWOPI2, v2);
    float tl, th; upk(tl, th, t2);
    if (tl < 0.0f) tl += TWOPI_F;
    if (th < 0.0f) th += TWOPI_F;
    g_lo = tl; g_hi = th;
    // ---- lq: center x, 2-term lattice  p = 1 + w*exp(a|u|) ----
    u64 k2  = add2(fma2(x2, INV2PI2, MG2), NMG2);
    u64 r2  = fma2(k2, NTWOPI2, x2);
    uacc2 = fma2(mul2(r2, r2), i2, uacc2);
    float cl, ch; upk(cl, ch, mul2(r2, b2));
    P2 = mul2(P2, fma2(w2, pk(ex2f(fabsf(cl)), ex2f(fabsf(ch))), ONE2));
}

struct Consts {
    u64 s01, s23, m01, m23, i01, i23, b01, b23, w01, w23;
};

// Finalize one element: both dim-pairs -> g stored, returns lq partial.
__device__ __forceinline__ float elem(const float4 e, const Consts& C,
                                      float4* __restrict__ gptr)
{
    float4 g;
    u64 u2 = 0, P2 = ONE2;
    dimpair(pk(e.x, e.y), C.s01, C.m01, C.i01, C.b01, C.w01, g.x, g.y, u2, P2);
    dimpair(pk(e.z, e.w), C.s23, C.m23, C.i23, C.b23, C.w23, g.z, g.w, u2, P2);
    *gptr = g;
    float u0, u1, p0, p1;
    upk(u0, u1, u2); upk(p0, p1, P2);
    return fmaf(u0 + u1, -0.5f, LN2_F * lg2f(p0 * p1));
}

// Pass 2: 2^18 threads.  Thread t owns dims [4*dq,4*dq+4) of FOUR (n,m)
// pairs sharing the same m: MC samples n, n+8, n+16, n+24.  All 9 loads are
// independent and front-batched -> high MLP; consts amortized 4x; the four
// element chains give 4-way ILP over the MUFU/FMA latencies.
__global__ void __launch_bounds__(256) relie_main(
    const float4* __restrict__ eps4,   // 2^20 float4
    const float4* __restrict__ mu4,    // M*4 float4
    float4*       __restrict__ g4,     // 2^20 float4
    float*        __restrict__ lq)     // N*M floats
{
    int t   = blockIdx.x * blockDim.x + threadIdx.x;  // 0 .. 2^18-1
    int nmA = t >> 2;
    int dq  = t & 3;
    int m   = nmA & (M - 1);
    int ci  = (m << 2) + dq;
    const int EST = 1 << 18;        // float4 stride between n-groups of 8
    const int NST = 8 * M;          // nm stride between n-groups of 8

    // Front-batched independent loads (4 eps + 5 consts)
    float4 e0 = eps4[t];
    float4 e1 = eps4[t +     EST];
    float4 e2 = eps4[t + 2 * EST];
    float4 e3 = eps4[t + 3 * EST];
    float4 mu = mu4[ci];
    float4 S  = reinterpret_cast<const float4*>(g_S )[ci];
    float4 I2 = reinterpret_cast<const float4*>(g_I2)[ci];
    float4 W  = reinterpret_cast<const float4*>(g_W )[ci];
    float4 B  = reinterpret_cast<const float4*>(g_B )[ci];

    Consts C;
    C.s01 = pk(S.x,  S.y);  C.s23 = pk(S.z,  S.w);
    C.m01 = pk(mu.x, mu.y); C.m23 = pk(mu.z, mu.w);
    C.i01 = pk(I2.x, I2.y); C.i23 = pk(I2.z, I2.w);
    C.b01 = pk(B.x,  B.y);  C.b23 = pk(B.z,  B.w);
    C.w01 = pk(W.x,  W.y);  C.w23 = pk(W.z,  W.w);

    float v0 = elem(e0, C, g4 + t);
    float v1 = elem(e1, C, g4 + t +     EST);
    float v2 = elem(e2, C, g4 + t + 2 * EST);
    float v3 = elem(e3, C, g4 + t + 3 * EST);

    // Reduce each element's partial across the 4 lanes owning its (n,m)
    v0 += __shfl_xor_sync(0xffffffffu, v0, 1);
    v0 += __shfl_xor_sync(0xffffffffu, v0, 2);
    v1 += __shfl_xor_sync(0xffffffffu, v1, 1);
    v1 += __shfl_xor_sync(0xffffffffu, v1, 2);
    v2 += __shfl_xor_sync(0xffffffffu, v2, 1);
    v2 += __shfl_xor_sync(0xffffffffu, v2, 2);
    v3 += __shfl_xor_sync(0xffffffffu, v3, 1);
    v3 += __shfl_xor_sync(0xffffffffu, v3, 2);
    if (dq == 0) {
        float Cm = g_C[m];
        lq[nmA          ] = v0 + Cm;
        lq[nmA +     NST] = v1 + Cm;
        lq[nmA + 2 * NST] = v2 + Cm;
        lq[nmA + 3 * NST] = v3 + Cm;
    }
}

extern "C" void kernel_launch(void* const* d_in, const int* in_sizes, int n_in,
                              void* d_out, int out_size) {
    const float* eps       = (const float*)d_in[0];  // (32, 8192, 16)
    const float* gamma_raw = (const float*)d_in[1];  // (8192, 16)
    const float* mu        = (const float*)d_in[2];  // (8192, 16)

    float* g_out  = (float*)d_out;                          // N*M*D floats
    float* lq_out = (float*)d_out + (size_t)N_MC * M * D;   // N*M floats

    relie_prep<<<(M * D) / 256, 256>>>(gamma_raw);
    relie_main<<<(1 << 18) / 256, 256>>>(
        (const float4*)eps, (const float4*)mu, (float4*)g_out, lq_out);
}

// round 7
// speedup vs baseline: 1.2440x; 1.0179x over previous
#include <cuda_runtime.h>

// Problem constants
static constexpr int N_MC = 32;
static constexpr int M    = 8192;
static constexpr int D    = 16;

#define TWOPI_F   6.2831853071795864769f   // rounds to float32(2*pi)
#define NEG_HALF_LOG_2PI -0.9189385332046727f
#define C_EX2     (-0.72134752044448170368f)  // -0.5 * log2(e)
#define LN2_F     0.69314718055994530942f
#define LOG2E_F   1.4426950408889634074f

typedef unsigned long long u64;

// Packed f32x2 broadcast constants (same f32 bits in both lanes)
#define MG2     0x4B4000004B400000ull   // ( 1.5*2^23,  1.5*2^23)
#define NMG2    0xCB400000CB400000ull   // (-1.5*2^23, -1.5*2^23)
#define INV2PI2 0x3E22F9833E22F983ull   // (1/2pi, 1/2pi)
#define NTWOPI2 0xC0C90FDBC0C90FDBull   // (-2pi, -2pi)
#define ONE2    0x3F8000003F800000ull   // (1, 1)

__device__ __forceinline__ float ex2f(float x) {
    float y; asm("ex2.approx.f32 %0, %1;" : "=f"(y) : "f"(x)); return y;
}
__device__ __forceinline__ float lg2f(float x) {
    float y; asm("lg2.approx.f32 %0, %1;" : "=f"(y) : "f"(x)); return y;
}
__device__ __forceinline__ u64 pk(float lo, float hi) {
    u64 r; asm("mov.b64 %0, {%1, %2};" : "=l"(r) : "f"(lo), "f"(hi)); return r;
}
__device__ __forceinline__ void upk(float& lo, float& hi, u64 v) {
    asm("mov.b64 {%0, %1}, %2;" : "=f"(lo), "=f"(hi) : "l"(v));
}
__device__ __forceinline__ u64 fma2(u64 a, u64 b, u64 c) {
    u64 d; asm("fma.rn.f32x2 %0, %1, %2, %3;" : "=l"(d) : "l"(a), "l"(b), "l"(c)); return d;
}
__device__ __forceinline__ u64 add2(u64 a, u64 b) {
    u64 d; asm("add.rn.f32x2 %0, %1, %2;" : "=l"(d) : "l"(a), "l"(b)); return d;
}
__device__ __forceinline__ u64 mul2(u64 a, u64 b) {
    u64 d; asm("mul.rn.f32x2 %0, %1, %2;" : "=l"(d) : "l"(a), "l"(b)); return d;
}

struct Consts {
    u64 s01, s23, m01, m23, i01, i23, b01, b23, w01, w23;
};

// One dim-PAIR, fully packed f32x2 (validated R5/R6: g bit-safe, lq 2-term).
__device__ __forceinline__ void dimpair(
    u64 e2, u64 s2, u64 mu2, u64 i2, u64 b2, u64 w2,
    float& g_lo, float& g_hi, u64& uacc2, u64& P2)
{
    u64 x2 = mul2(e2, s2);
    // ---- g = mod(x+mu, 2pi): magic-rint + exact fma remainder ----
    u64 v2 = add2(x2, mu2);
    u64 q2 = add2(fma2(v2, INV2PI2, MG2), NMG2);
    u64 t2 = fma2(q2, NTWOPI2, v2);
    float tl, th; upk(tl, th, t2);
    if (tl < 0.0f) tl += TWOPI_F;
    if (th < 0.0f) th += TWOPI_F;
    g_lo = tl; g_hi = th;
    // ---- lq: center x, 2-term lattice  p = 1 + w*exp(a|u|) ----
    u64 k2  = add2(fma2(x2, INV2PI2, MG2), NMG2);
    u64 r2  = fma2(k2, NTWOPI2, x2);
    uacc2 = fma2(mul2(r2, r2), i2, uacc2);
    float cl, ch; upk(cl, ch, mul2(r2, b2));
    P2 = mul2(P2, fma2(w2, pk(ex2f(fabsf(cl)), ex2f(fabsf(ch))), ONE2));
}

__device__ __forceinline__ float elem(const float4 e, const Consts& C,
                                      float4* __restrict__ gptr)
{
    float4 g;
    u64 u2 = 0, P2 = ONE2;
    dimpair(pk(e.x, e.y), C.s01, C.m01, C.i01, C.b01, C.w01, g.x, g.y, u2, P2);
    dimpair(pk(e.z, e.w), C.s23, C.m23, C.i23, C.b23, C.w23, g.z, g.w, u2, P2);
    *gptr = g;
    float u0, u1, p0, p1;
    upk(u0, u1, u2); upk(p0, p1, P2);
    return fmaf(u0 + u1, -0.5f, LN2_F * lg2f(p0 * p1));
}

// Single fused kernel: 131072 threads (512 blocks).  Thread (q, c) with
// c = m*4 + dq owns dims [4dq, 4dq+4) of MC samples n in [8q, 8q+8).
// Per-(m,d) constants are computed IN REGISTERS (precise softplus, so the
// bit-exact g path is preserved); C_m comes from a shfl over the dq quad.
// No prep kernel, no scratch arrays, one launch.
__global__ void __launch_bounds__(256) relie_fused(
    const float4* __restrict__ eps4,    // 2^20 float4  (n, m, d)
    const float4* __restrict__ gam4,    // M*4 float4
    const float4* __restrict__ mu4,     // M*4 float4
    float4*       __restrict__ g4,      // 2^20 float4
    float*        __restrict__ lq)      // N*M floats
{
    int tid = blockIdx.x * blockDim.x + threadIdx.x;  // 0 .. 2^17-1
    int q   = tid >> 15;                 // n-quarter: n0 = 8q
    int c   = tid & 0x7FFF;              // m*4 + dq
    int m   = c >> 2;
    int dq  = c & 3;
    int n0  = q << 3;

    // ---- per-(m,d) constants, 4 dims, in registers ----
    float4 gam = gam4[c];
    float4 mu  = mu4[c];
    float gv[4] = { gam.x, gam.y, gam.z, gam.w };
    float sv[4], iv[4], wv[4], bv[4];
    float ln = 0.0f;
    #pragma unroll
    for (int j = 0; j < 4; j++) {
        float raw = gv[j];
        // EXACT jax.nn.softplus: max(x,0) + log1p(exp(-|x|)), precise libdevice
        float s   = fmaxf(raw, 0.0f) + log1pf(expf(-fabsf(raw)));
        float inv = 1.0f / s;
        float a   = TWOPI_F * inv;
        sv[j] = s;
        iv[j] = inv * inv;
        wv[j] = ex2f(a * a * C_EX2);     // exp(-a^2/2)
        bv[j] = a * inv * LOG2E_F;       // c = r*b = (a*u)*log2(e)
        ln += NEG_HALF_LOG_2PI - LN2_F * lg2f(s);
    }
    // C_m = sum over all 16 dims: reduce over the dq quad (lane&3 == dq)
    ln += __shfl_xor_sync(0xffffffffu, ln, 1);
    ln += __shfl_xor_sync(0xffffffffu, ln, 2);
    float Cm = ln;

    Consts C;
    C.s01 = pk(sv[0], sv[1]); C.s23 = pk(sv[2], sv[3]);
    C.m01 = pk(mu.x,  mu.y);  C.m23 = pk(mu.z,  mu.w);
    C.i01 = pk(iv[0], iv[1]); C.i23 = pk(iv[2], iv[3]);
    C.b01 = pk(bv[0], bv[1]); C.b23 = pk(bv[2], bv[3]);
    C.w01 = pk(wv[0], wv[1]); C.w23 = pk(wv[2], wv[3]);

    // ---- 8 elements: front-batched independent loads (MLP = 8) ----
    const int ROW = M * 4;               // float4 stride per MC sample
    int base = n0 * ROW + c;
    float4 e[8];
    #pragma unroll
    for (int i = 0; i < 8; i++) e[i] = eps4[base + i * ROW];

    float v[8];
    #pragma unroll
    for (int i = 0; i < 8; i++) v[i] = elem(e[i], C, g4 + base + i * ROW);

    // ---- lq reductions over the dq quad, one per MC sample ----
    #pragma unroll
    for (int i = 0; i < 8; i++) {
        float x = v[i];
        x += __shfl_xor_sync(0xffffffffu, x, 1);
        x += __shfl_xor_sync(0xffffffffu, x, 2);
        v[i] = x;
    }
    if (dq == 0) {
        int nm = n0 * M + m;
        #pragma unroll
        for (int i = 0; i < 8; i++) lq[nm + i * M] = v[i] + Cm;
    }
}

extern "C" void kernel_launch(void* const* d_in, const int* in_sizes, int n_in,
                              void* d_out, int out_size) {
    const float* eps       = (const float*)d_in[0];  // (32, 8192, 16)
    const float* gamma_raw = (const float*)d_in[1];  // (8192, 16)
    const float* mu        = (const float*)d_in[2];  // (8192, 16)

    float* g_out  = (float*)d_out;                          // N*M*D floats
    float* lq_out = (float*)d_out + (size_t)N_MC * M * D;   // N*M floats

    relie_fused<<<(1 << 17) / 256, 256>>>(
        (const float4*)eps, (const float4*)gamma_raw, (const float4*)mu,
        (float4*)g_out, lq_out);
}